// round 11
// baseline (speedup 1.0000x reference)
#include <cuda_runtime.h>
#include <cstdint>

// Problem constants (fixed by the reference implementation)
#define NFEAT  23
#define EMB    10
#define TOTALD 65      // sum(FEATURE_DIMS)
#define DMAXD  4
#define CH     230     // NFEAT * EMB
#define PAIRS  115     // CH / 2 — each thread owns an (e, e+1) pair of one feature
#define TR     32      // rows per smem tile
#define NTILES 8
#define RPB    (TR * NTILES)            // 256 rows per block
#define PIPE   3                        // bulk-copy ring depth
#define TILE_BYTES (TR * TOTALD * 4)    // 8320 B (multiple of 16)

__constant__ int c_dims[NFEAT] = {4,4,4,4,4,4,4,4,4,4,4,4,2,2,1,4,1,1,1,1,1,1,2};
__constant__ int c_offs[NFEAT] = {0,4,8,12,16,20,24,28,32,36,40,44,48,50,52,53,57,58,59,60,61,62,63};

// ---- mbarrier + bulk-copy helpers (one UBLKCP per tile: zero LSU cost) ----
__device__ __forceinline__ uint32_t smem_u32(const void* p) {
    return (uint32_t)__cvta_generic_to_shared(p);
}
__device__ __forceinline__ void mbar_init(uint32_t mbar, uint32_t count) {
    asm volatile("mbarrier.init.shared.b64 [%0], %1;" :: "r"(mbar), "r"(count) : "memory");
}
__device__ __forceinline__ void mbar_expect_tx(uint32_t mbar, uint32_t bytes) {
    asm volatile("mbarrier.arrive.expect_tx.shared.b64 _, [%0], %1;"
                 :: "r"(mbar), "r"(bytes) : "memory");
}
__device__ __forceinline__ void bulk_g2s(uint32_t dst_s, const void* src,
                                         uint32_t bytes, uint32_t mbar) {
    asm volatile(
        "cp.async.bulk.shared::cta.global.mbarrier::complete_tx::bytes "
        "[%0], [%1], %2, [%3];"
        :: "r"(dst_s), "l"(src), "r"(bytes), "r"(mbar) : "memory");
}
__device__ __forceinline__ void mbar_wait(uint32_t mbar, uint32_t parity) {
    asm volatile(
        "{\n\t"
        ".reg .pred P;\n\t"
        "WAIT_%=:\n\t"
        "mbarrier.try_wait.parity.acquire.cta.shared::cta.b64 P, [%0], %1, 0x989680;\n\t"
        "@P bra.uni DONE_%=;\n\t"
        "bra.uni WAIT_%=;\n\t"
        "DONE_%=:\n\t"
        "}"
        :: "r"(mbar), "r"(parity) : "memory");
}

// blockDim=256: tid%128 = channel-pair index p (0..114 active), tid/128 = row
// phase. Per block: 8 contiguous 32-row tiles through a 3-deep bulk-DMA ring,
// so each tile's transfer is issued TWO compute phases before its wait (DRAM
// latency fully covered). Compute stores with coalesced 256B/warp float2
// streaming stores. RPB=256 halves per-block fixed costs (mbarrier init,
// cold-prefetch ramp, weight prologue) vs the RPB=128 variant.
__global__ __launch_bounds__(256, 8)
void Projection_5171140624940_kernel(const float* __restrict__ x,
                                     const float* __restrict__ W,
                                     const float* __restrict__ b,
                                     float* __restrict__ out,
                                     int rows)
{
    __shared__ __align__(16) float xs[PIPE][TR * TOTALD];   // 3 x 8320 B
    __shared__ __align__(8)  uint64_t mb[PIPE];

    const int tid   = threadIdx.x;
    const int p     = tid & 127;
    const int rslot = tid >> 7;
    const bool active = (p < PAIRS);

    // Per-thread channel-pair metadata + register-resident weights.
    float w0[DMAXD], w1[DMAXD];
    float b0 = 0.f, b1 = 0.f;
    int off = 0, dim = 0;
    if (active) {
        const int f = p / 5;
        const int e = (p - f * 5) * 2;
        off = c_offs[f];
        dim = c_dims[f];
        #pragma unroll
        for (int j = 0; j < DMAXD; ++j) {
            w0[j] = __ldg(W + f * (DMAXD * EMB) + j * EMB + e);
            w1[j] = __ldg(W + f * (DMAXD * EMB) + j * EMB + e + 1);
        }
        b0 = __ldg(b + f * EMB + e);
        b1 = __ldg(b + f * EMB + e + 1);
    }

    const int rBase = blockIdx.x * RPB;

    if (rBase + RPB <= rows) {
        // ---- Fast path: 8 full tiles through the 3-slot DMA ring ----
        uint32_t mbs[PIPE], xss[PIPE];
        #pragma unroll
        for (int s = 0; s < PIPE; ++s) {
            mbs[s] = smem_u32(&mb[s]);
            xss[s] = smem_u32(xs[s]);
        }

        if (tid == 0) {
            #pragma unroll
            for (int s = 0; s < PIPE; ++s) mbar_init(mbs[s], 1);
            asm volatile("fence.proxy.async.shared::cta;" ::: "memory");
        }
        __syncthreads();

        // Prefetch tiles 0 and 1 (two-deep head start).
        if (tid == 0) {
            #pragma unroll
            for (int k = 0; k < PIPE - 1; ++k) {
                mbar_expect_tx(mbs[k], TILE_BYTES);
                bulk_g2s(xss[k], x + (size_t)(rBase + k * TR) * TOTALD,
                         TILE_BYTES, mbs[k]);
            }
        }

        #pragma unroll
        for (int t = 0; t < NTILES; ++t) {
            const int slot = t % PIPE;
            // Issue tile t+2 into slot (t+2)%PIPE. Its last reader (tile t-1)
            // finished before the end-of-iteration barrier of iter t-1, and
            // its mbarrier's last waiter also passed before that barrier.
            if (tid == 0 && t + (PIPE - 1) < NTILES) {
                const int ps = (t + PIPE - 1) % PIPE;
                mbar_expect_tx(mbs[ps], TILE_BYTES);
                bulk_g2s(xss[ps],
                         x + (size_t)(rBase + (t + PIPE - 1) * TR) * TOTALD,
                         TILE_BYTES, mbs[ps]);
            }
            // Wait for tile t; slot reused every PIPE tiles -> parity flips.
            mbar_wait(mbs[slot], (t / PIPE) & 1);

            if (active) {
                const int tileStart = rBase + t * TR;
                const float* xb = xs[slot];
                #pragma unroll 4
                for (int lr = rslot; lr < TR; lr += 2) {
                    const float* xr = xb + lr * TOTALD + off;
                    float s0 = b0, s1 = b1;
                    #pragma unroll
                    for (int j = 0; j < DMAXD; ++j) {
                        if (j < dim) {
                            const float xv = xr[j];
                            s0 = fmaf(xv, w0[j], s0);
                            s1 = fmaf(xv, w1[j], s1);
                        }
                    }
                    // warp writes 256B contiguous; .cs streams past L2
                    __stcs(reinterpret_cast<float2*>(
                               out + (size_t)(tileStart + lr) * CH + 2 * p),
                           make_float2(s0, s1));
                }
            }
            __syncthreads();   // last read of xs[slot]; refilled at iter t+1
        }
    } else {
        // ---- Tail path (unused for B=524288): synchronous staging ----
        for (int t0 = 0; t0 < RPB; t0 += TR) {
            const int tileStart = rBase + t0;
            if (tileStart >= rows) break;
            const int tileRows = min(TR, rows - tileStart);

            const float* src = x + (size_t)tileStart * TOTALD;
            for (int i = tid; i < tileRows * TOTALD; i += 256)
                xs[0][i] = __ldcs(src + i);
            __syncthreads();

            if (active) {
                for (int lr = rslot; lr < tileRows; lr += 2) {
                    const float* xr = xs[0] + lr * TOTALD + off;
                    float s0 = b0, s1 = b1;
                    #pragma unroll
                    for (int j = 0; j < DMAXD; ++j) {
                        if (j < dim) {
                            const float xv = xr[j];
                            s0 = fmaf(xv, w0[j], s0);
                            s1 = fmaf(xv, w1[j], s1);
                        }
                    }
                    __stcs(reinterpret_cast<float2*>(
                               out + (size_t)(tileStart + lr) * CH + 2 * p),
                           make_float2(s0, s1));
                }
            }
            __syncthreads();
        }
    }
}

extern "C" void kernel_launch(void* const* d_in, const int* in_sizes, int n_in,
                              void* d_out, int out_size)
{
    const float* x = (const float*)d_in[0];   // [B, 65] f32
    const float* W = (const float*)d_in[1];   // [23, 4, 10] f32 (masked)
    const float* b = (const float*)d_in[2];   // [23, 10] f32
    // d_in[3] = idx (int32) — compile-time constant metadata, ignored.
    float* out = (float*)d_out;               // [B, 23, 10] f32

    const int rows = in_sizes[0] / TOTALD;    // 524288
    const int grid = (rows + RPB - 1) / RPB;  // 2048

    Projection_5171140624940_kernel<<<grid, 256>>>(x, W, b, out, rows);
}

// round 12
// speedup vs baseline: 1.0380x; 1.0380x over previous
#include <cuda_runtime.h>
#include <cstdint>

// Problem constants (fixed by the reference implementation)
#define NFEAT  23
#define EMB    10
#define TOTALD 65      // sum(FEATURE_DIMS)
#define DMAXD  4
#define CH     230     // NFEAT * EMB
#define PAIRS  115     // CH / 2 — each thread owns an (e, e+1) pair of one feature
#define TR     32      // rows per smem tile
#define NTILES 4
#define RPB    (TR * NTILES)            // 128 rows per block
#define PIPE   3                        // bulk-copy ring depth
#define TILE_BYTES (TR * TOTALD * 4)    // 8320 B (multiple of 16)

__constant__ int c_dims[NFEAT] = {4,4,4,4,4,4,4,4,4,4,4,4,2,2,1,4,1,1,1,1,1,1,2};
__constant__ int c_offs[NFEAT] = {0,4,8,12,16,20,24,28,32,36,40,44,48,50,52,53,57,58,59,60,61,62,63};

// ---- mbarrier + bulk-copy helpers (one UBLKCP per tile: zero LSU cost) ----
__device__ __forceinline__ uint32_t smem_u32(const void* p) {
    return (uint32_t)__cvta_generic_to_shared(p);
}
__device__ __forceinline__ void mbar_init(uint32_t mbar, uint32_t count) {
    asm volatile("mbarrier.init.shared.b64 [%0], %1;" :: "r"(mbar), "r"(count) : "memory");
}
__device__ __forceinline__ void mbar_expect_tx(uint32_t mbar, uint32_t bytes) {
    asm volatile("mbarrier.arrive.expect_tx.shared.b64 _, [%0], %1;"
                 :: "r"(mbar), "r"(bytes) : "memory");
}
__device__ __forceinline__ void bulk_g2s(uint32_t dst_s, const void* src,
                                         uint32_t bytes, uint32_t mbar) {
    asm volatile(
        "cp.async.bulk.shared::cta.global.mbarrier::complete_tx::bytes "
        "[%0], [%1], %2, [%3];"
        :: "r"(dst_s), "l"(src), "r"(bytes), "r"(mbar) : "memory");
}
__device__ __forceinline__ void mbar_wait(uint32_t mbar, uint32_t parity) {
    asm volatile(
        "{\n\t"
        ".reg .pred P;\n\t"
        "WAIT_%=:\n\t"
        "mbarrier.try_wait.parity.acquire.cta.shared::cta.b64 P, [%0], %1, 0x989680;\n\t"
        "@P bra.uni DONE_%=;\n\t"
        "bra.uni WAIT_%=;\n\t"
        "DONE_%=:\n\t"
        "}"
        :: "r"(mbar), "r"(parity) : "memory");
}

// blockDim=256: tid%128 = channel-pair index p (0..114 active), tid/128 = row
// phase. Per block: 4 contiguous 32-row tiles through a 3-deep bulk-DMA ring
// (each tile's transfer issued two compute phases before its wait). Compute
// stores with coalesced 256B/warp float2 WRITE-BACK stores (vs .cs in prior
// rounds: default policy lets LTS buffer/combine the write stream, which is
// 78% of total traffic).
__global__ __launch_bounds__(256, 8)
void Projection_5171140624940_kernel(const float* __restrict__ x,
                                     const float* __restrict__ W,
                                     const float* __restrict__ b,
                                     float* __restrict__ out,
                                     int rows)
{
    __shared__ __align__(16) float xs[PIPE][TR * TOTALD];   // 3 x 8320 B
    __shared__ __align__(8)  uint64_t mb[PIPE];

    const int tid   = threadIdx.x;
    const int p     = tid & 127;
    const int rslot = tid >> 7;
    const bool active = (p < PAIRS);

    // Per-thread channel-pair metadata + register-resident weights.
    float w0[DMAXD], w1[DMAXD];
    float b0 = 0.f, b1 = 0.f;
    int off = 0, dim = 0;
    if (active) {
        const int f = p / 5;
        const int e = (p - f * 5) * 2;
        off = c_offs[f];
        dim = c_dims[f];
        #pragma unroll
        for (int j = 0; j < DMAXD; ++j) {
            w0[j] = __ldg(W + f * (DMAXD * EMB) + j * EMB + e);
            w1[j] = __ldg(W + f * (DMAXD * EMB) + j * EMB + e + 1);
        }
        b0 = __ldg(b + f * EMB + e);
        b1 = __ldg(b + f * EMB + e + 1);
    }

    const int rBase = blockIdx.x * RPB;

    if (rBase + RPB <= rows) {
        // ---- Fast path: 4 full tiles through the 3-slot DMA ring ----
        uint32_t mbs[PIPE], xss[PIPE];
        #pragma unroll
        for (int s = 0; s < PIPE; ++s) {
            mbs[s] = smem_u32(&mb[s]);
            xss[s] = smem_u32(xs[s]);
        }

        if (tid == 0) {
            #pragma unroll
            for (int s = 0; s < PIPE; ++s) mbar_init(mbs[s], 1);
            asm volatile("fence.proxy.async.shared::cta;" ::: "memory");
        }
        __syncthreads();

        // Prefetch tiles 0 and 1 (two-deep head start).
        if (tid == 0) {
            #pragma unroll
            for (int k = 0; k < PIPE - 1; ++k) {
                mbar_expect_tx(mbs[k], TILE_BYTES);
                bulk_g2s(xss[k], x + (size_t)(rBase + k * TR) * TOTALD,
                         TILE_BYTES, mbs[k]);
            }
        }

        #pragma unroll
        for (int t = 0; t < NTILES; ++t) {
            const int slot = t % PIPE;
            // Issue tile t+2 into slot (t+2)%PIPE. Its last reader (tile t-1)
            // finished before the end-of-iteration barrier of iter t-1, and
            // its mbarrier's last waiter also passed before that barrier.
            if (tid == 0 && t + (PIPE - 1) < NTILES) {
                const int ps = (t + PIPE - 1) % PIPE;
                mbar_expect_tx(mbs[ps], TILE_BYTES);
                bulk_g2s(xss[ps],
                         x + (size_t)(rBase + (t + PIPE - 1) * TR) * TOTALD,
                         TILE_BYTES, mbs[ps]);
            }
            // Wait for tile t; slot reused every PIPE tiles -> parity flips.
            mbar_wait(mbs[slot], (t / PIPE) & 1);

            if (active) {
                const int tileStart = rBase + t * TR;
                const float* xb = xs[slot];
                #pragma unroll 4
                for (int lr = rslot; lr < TR; lr += 2) {
                    const float* xr = xb + lr * TOTALD + off;
                    float s0 = b0, s1 = b1;
                    #pragma unroll
                    for (int j = 0; j < DMAXD; ++j) {
                        if (j < dim) {
                            const float xv = xr[j];
                            s0 = fmaf(xv, w0[j], s0);
                            s1 = fmaf(xv, w1[j], s1);
                        }
                    }
                    // warp writes 256B contiguous; default write-back policy
                    *reinterpret_cast<float2*>(
                        out + (size_t)(tileStart + lr) * CH + 2 * p) =
                        make_float2(s0, s1);
                }
            }
            __syncthreads();   // last read of xs[slot]; refilled at iter t+1
        }
    } else {
        // ---- Tail path (unused for B=524288): synchronous staging ----
        for (int t0 = 0; t0 < RPB; t0 += TR) {
            const int tileStart = rBase + t0;
            if (tileStart >= rows) break;
            const int tileRows = min(TR, rows - tileStart);

            const float* src = x + (size_t)tileStart * TOTALD;
            for (int i = tid; i < tileRows * TOTALD; i += 256)
                xs[0][i] = __ldcs(src + i);
            __syncthreads();

            if (active) {
                for (int lr = rslot; lr < tileRows; lr += 2) {
                    const float* xr = xs[0] + lr * TOTALD + off;
                    float s0 = b0, s1 = b1;
                    #pragma unroll
                    for (int j = 0; j < DMAXD; ++j) {
                        if (j < dim) {
                            const float xv = xr[j];
                            s0 = fmaf(xv, w0[j], s0);
                            s1 = fmaf(xv, w1[j], s1);
                        }
                    }
                    *reinterpret_cast<float2*>(
                        out + (size_t)(tileStart + lr) * CH + 2 * p) =
                        make_float2(s0, s1);
                }
            }
            __syncthreads();
        }
    }
}

extern "C" void kernel_launch(void* const* d_in, const int* in_sizes, int n_in,
                              void* d_out, int out_size)
{
    const float* x = (const float*)d_in[0];   // [B, 65] f32
    const float* W = (const float*)d_in[1];   // [23, 4, 10] f32 (masked)
    const float* b = (const float*)d_in[2];   // [23, 10] f32
    // d_in[3] = idx (int32) — compile-time constant metadata, ignored.
    float* out = (float*)d_out;               // [B, 23, 10] f32

    const int rows = in_sizes[0] / TOTALD;    // 524288
    const int grid = (rows + RPB - 1) / RPB;  // 4096

    Projection_5171140624940_kernel<<<grid, 256>>>(x, W, b, out, rows);
}

// round 13
// speedup vs baseline: 1.0453x; 1.0070x over previous
#include <cuda_runtime.h>
#include <cstdint>

// Problem constants (fixed by the reference implementation)
#define NFEAT  23
#define EMB    10
#define TOTALD 65      // sum(FEATURE_DIMS)
#define DMAXD  4
#define CH     230     // NFEAT * EMB
#define PAIRS  115     // CH / 2 — each thread owns an (e, e+1) pair of one feature
#define TR     64      // rows per smem tile (2x prior: halves sync/DMA counts)
#define NTILES 2
#define RPB    (TR * NTILES)            // 128 rows per block
#define PIPE   2                        // bulk-copy ring depth
#define TILE_BYTES (TR * TOTALD * 4)    // 16640 B (multiple of 16)

__constant__ int c_dims[NFEAT] = {4,4,4,4,4,4,4,4,4,4,4,4,2,2,1,4,1,1,1,1,1,1,2};
__constant__ int c_offs[NFEAT] = {0,4,8,12,16,20,24,28,32,36,40,44,48,50,52,53,57,58,59,60,61,62,63};

// ---- mbarrier + bulk-copy helpers (one UBLKCP per tile: zero LSU cost) ----
__device__ __forceinline__ uint32_t smem_u32(const void* p) {
    return (uint32_t)__cvta_generic_to_shared(p);
}
__device__ __forceinline__ void mbar_init(uint32_t mbar, uint32_t count) {
    asm volatile("mbarrier.init.shared.b64 [%0], %1;" :: "r"(mbar), "r"(count) : "memory");
}
__device__ __forceinline__ void mbar_expect_tx(uint32_t mbar, uint32_t bytes) {
    asm volatile("mbarrier.arrive.expect_tx.shared.b64 _, [%0], %1;"
                 :: "r"(mbar), "r"(bytes) : "memory");
}
__device__ __forceinline__ void bulk_g2s(uint32_t dst_s, const void* src,
                                         uint32_t bytes, uint32_t mbar) {
    asm volatile(
        "cp.async.bulk.shared::cta.global.mbarrier::complete_tx::bytes "
        "[%0], [%1], %2, [%3];"
        :: "r"(dst_s), "l"(src), "r"(bytes), "r"(mbar) : "memory");
}
__device__ __forceinline__ void mbar_wait(uint32_t mbar, uint32_t parity) {
    asm volatile(
        "{\n\t"
        ".reg .pred P;\n\t"
        "WAIT_%=:\n\t"
        "mbarrier.try_wait.parity.acquire.cta.shared::cta.b64 P, [%0], %1, 0x989680;\n\t"
        "@P bra.uni DONE_%=;\n\t"
        "bra.uni WAIT_%=;\n\t"
        "DONE_%=:\n\t"
        "}"
        :: "r"(mbar), "r"(parity) : "memory");
}

// blockDim=256: tid%128 = channel-pair index p (0..114 active), tid/128 = row
// phase. Per block: 2 contiguous 64-row tiles, double-buffered bulk-DMA.
// Larger tiles halve the per-row mbarrier-wait and __syncthreads counts vs
// the TR=32 variant; the ~2000-cycle compute phase covers the one-ahead
// prefetch latency. Stores: coalesced 256B/warp float2 streaming stores.
__global__ __launch_bounds__(256, 6)
void Projection_5171140624940_kernel(const float* __restrict__ x,
                                     const float* __restrict__ W,
                                     const float* __restrict__ b,
                                     float* __restrict__ out,
                                     int rows)
{
    __shared__ __align__(16) float xs[PIPE][TR * TOTALD];   // 2 x 16640 B
    __shared__ __align__(8)  uint64_t mb[PIPE];

    const int tid   = threadIdx.x;
    const int p     = tid & 127;
    const int rslot = tid >> 7;
    const bool active = (p < PAIRS);

    // Per-thread channel-pair metadata + register-resident weights.
    float w0[DMAXD], w1[DMAXD];
    float b0 = 0.f, b1 = 0.f;
    int off = 0, dim = 0;
    if (active) {
        const int f = p / 5;
        const int e = (p - f * 5) * 2;
        off = c_offs[f];
        dim = c_dims[f];
        #pragma unroll
        for (int j = 0; j < DMAXD; ++j) {
            w0[j] = __ldg(W + f * (DMAXD * EMB) + j * EMB + e);
            w1[j] = __ldg(W + f * (DMAXD * EMB) + j * EMB + e + 1);
        }
        b0 = __ldg(b + f * EMB + e);
        b1 = __ldg(b + f * EMB + e + 1);
    }

    const int rBase = blockIdx.x * RPB;

    if (rBase + RPB <= rows) {
        // ---- Fast path: 2 full tiles, double-buffered DMA ----
        const uint32_t mbs[PIPE] = { smem_u32(&mb[0]), smem_u32(&mb[1]) };
        const uint32_t xss[PIPE] = { smem_u32(xs[0]),  smem_u32(xs[1])  };

        if (tid == 0) {
            mbar_init(mbs[0], 1);
            mbar_init(mbs[1], 1);
            asm volatile("fence.proxy.async.shared::cta;" ::: "memory");
        }
        __syncthreads();

        // Prefetch tile 0.
        if (tid == 0) {
            mbar_expect_tx(mbs[0], TILE_BYTES);
            bulk_g2s(xss[0], x + (size_t)rBase * TOTALD, TILE_BYTES, mbs[0]);
        }

        #pragma unroll
        for (int t = 0; t < NTILES; ++t) {
            const int slot = t & 1;
            // Issue tile t+1 into the other buffer (untouched since init /
            // last-iteration barrier).
            if (tid == 0 && t + 1 < NTILES) {
                mbar_expect_tx(mbs[slot ^ 1], TILE_BYTES);
                bulk_g2s(xss[slot ^ 1],
                         x + (size_t)(rBase + (t + 1) * TR) * TOTALD,
                         TILE_BYTES, mbs[slot ^ 1]);
            }
            // Wait for tile t (each barrier used once per block -> parity 0).
            mbar_wait(mbs[slot], 0);

            if (active) {
                const int tileStart = rBase + t * TR;
                const float* xb = xs[slot];
                #pragma unroll 4
                for (int lr = rslot; lr < TR; lr += 2) {
                    const float* xr = xb + lr * TOTALD + off;
                    float s0 = b0, s1 = b1;
                    #pragma unroll
                    for (int j = 0; j < DMAXD; ++j) {
                        if (j < dim) {
                            const float xv = xr[j];
                            s0 = fmaf(xv, w0[j], s0);
                            s1 = fmaf(xv, w1[j], s1);
                        }
                    }
                    // warp writes 256B contiguous; .cs streams past L2
                    __stcs(reinterpret_cast<float2*>(
                               out + (size_t)(tileStart + lr) * CH + 2 * p),
                           make_float2(s0, s1));
                }
            }
            if (t + 1 < NTILES) __syncthreads();   // order before next tile
        }
    } else {
        // ---- Tail path (unused for B=524288): synchronous staging ----
        for (int t0 = 0; t0 < RPB; t0 += TR) {
            const int tileStart = rBase + t0;
            if (tileStart >= rows) break;
            const int tileRows = min(TR, rows - tileStart);

            const float* src = x + (size_t)tileStart * TOTALD;
            for (int i = tid; i < tileRows * TOTALD; i += 256)
                xs[0][i] = __ldcs(src + i);
            __syncthreads();

            if (active) {
                for (int lr = rslot; lr < tileRows; lr += 2) {
                    const float* xr = xs[0] + lr * TOTALD + off;
                    float s0 = b0, s1 = b1;
                    #pragma unroll
                    for (int j = 0; j < DMAXD; ++j) {
                        if (j < dim) {
                            const float xv = xr[j];
                            s0 = fmaf(xv, w0[j], s0);
                            s1 = fmaf(xv, w1[j], s1);
                        }
                    }
                    __stcs(reinterpret_cast<float2*>(
                               out + (size_t)(tileStart + lr) * CH + 2 * p),
                           make_float2(s0, s1));
                }
            }
            __syncthreads();
        }
    }
}

extern "C" void kernel_launch(void* const* d_in, const int* in_sizes, int n_in,
                              void* d_out, int out_size)
{
    const float* x = (const float*)d_in[0];   // [B, 65] f32
    const float* W = (const float*)d_in[1];   // [23, 4, 10] f32 (masked)
    const float* b = (const float*)d_in[2];   // [23, 10] f32
    // d_in[3] = idx (int32) — compile-time constant metadata, ignored.
    float* out = (float*)d_out;               // [B, 23, 10] f32

    const int rows = in_sizes[0] / TOTALD;    // 524288
    const int grid = (rows + RPB - 1) / RPB;  // 4096

    Projection_5171140624940_kernel<<<grid, 256>>>(x, W, b, out, rows);
}